// round 1
// baseline (speedup 1.0000x reference)
#include <cuda_runtime.h>
#include <math.h>

#define B_ 128
#define T_ 512
#define F_ 256
#define H_ 512

// Scratch (device globals: allocation-free per harness rules)
__device__ float g_xproj[(size_t)T_ * 4 * B_ * H_];   // [T][gate][B][H], 512 MB
__device__ float g_h[2][B_ * H_];                      // double-buffered hidden state
__device__ float g_c[B_ * H_];
__device__ float g_n[B_ * H_];

// ---------------------------------------------------------------------------
// Zero the recurrent state (must happen every launch; graph replays reuse it)
// ---------------------------------------------------------------------------
__global__ void init_kernel() {
    int i = blockIdx.x * blockDim.x + threadIdx.x;
    if (i < B_ * H_) {
        g_h[0][i] = 0.f;
        g_c[i] = 0.f;
        g_n[i] = 0.f;
    }
}

// ---------------------------------------------------------------------------
// Input projections: y[t][g][b][h] = sum_f x[b][t][f] * Wg[f][h] + bg[h]
// x is exactly a [B*T, F] row-major matrix (row m = b*T + t).
// BM=64, BN=64, BK=16, 256 threads, 4x4 register tile, one gate per block.
// ---------------------------------------------------------------------------
__global__ __launch_bounds__(256) void proj_kernel(
    const float* __restrict__ x,
    const float* __restrict__ W0, const float* __restrict__ b0,
    const float* __restrict__ W1, const float* __restrict__ b1,
    const float* __restrict__ W2, const float* __restrict__ b2,
    const float* __restrict__ W3, const float* __restrict__ b3)
{
    const int g  = blockIdx.x >> 3;          // 4 gates
    const int n0 = (blockIdx.x & 7) * 64;    // h tile
    const int m0 = blockIdx.y * 64;          // (b,t) row tile

    const float* __restrict__ W    = (g == 0) ? W0 : (g == 1) ? W1 : (g == 2) ? W2 : W3;
    const float* __restrict__ bias = (g == 0) ? b0 : (g == 1) ? b1 : (g == 2) ? b2 : b3;

    __shared__ float As[16][64];   // [k][m]
    __shared__ float Bs[16][64];   // [k][n]

    const int tid = threadIdx.x;
    const int tx  = tid & 15;      // n: tx*4
    const int ty  = tid >> 4;      // m: ty*4

    // loader indices
    const int lm  = tid >> 2;         // 0..63
    const int lk4 = (tid & 3) * 4;    // 0,4,8,12
    const int wk  = tid >> 4;         // 0..15
    const int wn4 = (tid & 15) * 4;   // 0..60

    float acc[4][4] = {};

    for (int k0 = 0; k0 < F_; k0 += 16) {
        float4 xa = *(const float4*)&x[(size_t)(m0 + lm) * F_ + k0 + lk4];
        As[lk4 + 0][lm] = xa.x;
        As[lk4 + 1][lm] = xa.y;
        As[lk4 + 2][lm] = xa.z;
        As[lk4 + 3][lm] = xa.w;
        *(float4*)&Bs[wk][wn4] =
            *(const float4*)&W[(size_t)(k0 + wk) * H_ + n0 + wn4];
        __syncthreads();

#pragma unroll
        for (int k = 0; k < 16; k++) {
            float4 a = *(const float4*)&As[k][ty * 4];
            float4 b = *(const float4*)&Bs[k][tx * 4];
            float av[4] = {a.x, a.y, a.z, a.w};
            float bv[4] = {b.x, b.y, b.z, b.w};
#pragma unroll
            for (int i = 0; i < 4; i++)
#pragma unroll
                for (int j = 0; j < 4; j++)
                    acc[i][j] += av[i] * bv[j];
        }
        __syncthreads();
    }

#pragma unroll
    for (int i = 0; i < 4; i++) {
        int m = m0 + ty * 4 + i;
        int b = m >> 9;       // m / T_
        int t = m & 511;      // m % T_
        float* out = &g_xproj[(((size_t)t * 4 + g) * B_ + b) * H_ + n0 + tx * 4];
#pragma unroll
        for (int j = 0; j < 4; j++)
            out[j] = acc[i][j] + bias[n0 + tx * 4 + j];
    }
}

// ---------------------------------------------------------------------------
// One recurrent step: gates = xproj[t] + h_prev @ R{f,i,o,z}, then sLSTM update.
// BM=16 (batch), BN=32 (hidden), 4 gates fused per block, 128 threads,
// 2x2 register tile per gate. Grid: (H/32=16, B/16=8) = 128 blocks.
// ---------------------------------------------------------------------------
__global__ __launch_bounds__(128) void step_kernel(
    int t, int par,
    const float* __restrict__ Rf, const float* __restrict__ Ri,
    const float* __restrict__ Ro, const float* __restrict__ Rz)
{
    const int n0 = blockIdx.x * 32;
    const int m0 = blockIdx.y * 16;

    const float* __restrict__ h_in = g_h[par];
    float* __restrict__ h_out = g_h[par ^ 1];

    __shared__ float Hs[16][16];        // [k][m]
    __shared__ float Rs[4][16][32];     // [gate][k][n]

    const int tid = threadIdx.x;
    const int tx  = tid & 15;    // n: tx*2
    const int ty  = tid >> 4;    // m: ty*2 (0..7)

    // loader indices
    const int hm  = tid >> 3;          // 0..15
    const int hk2 = (tid & 7) * 2;     // 0..14
    const int rk  = tid >> 3;          // 0..15
    const int rn4 = (tid & 7) * 4;     // 0..28

    const float* __restrict__ Rg[4] = {Rf, Ri, Ro, Rz};

    float acc[4][2][2] = {};

    for (int k0 = 0; k0 < H_; k0 += 16) {
        float2 hv = *(const float2*)&h_in[(m0 + hm) * H_ + k0 + hk2];
        Hs[hk2 + 0][hm] = hv.x;
        Hs[hk2 + 1][hm] = hv.y;
#pragma unroll
        for (int g = 0; g < 4; g++)
            *(float4*)&Rs[g][rk][rn4] =
                *(const float4*)&Rg[g][(size_t)(k0 + rk) * H_ + n0 + rn4];
        __syncthreads();

#pragma unroll
        for (int k = 0; k < 16; k++) {
            float2 a = *(const float2*)&Hs[k][ty * 2];
#pragma unroll
            for (int g = 0; g < 4; g++) {
                float2 b = *(const float2*)&Rs[g][k][tx * 2];
                acc[g][0][0] += a.x * b.x;
                acc[g][0][1] += a.x * b.y;
                acc[g][1][0] += a.y * b.x;
                acc[g][1][1] += a.y * b.y;
            }
        }
        __syncthreads();
    }

    const float* __restrict__ xp = &g_xproj[(size_t)t * 4 * B_ * H_];

#pragma unroll
    for (int i = 0; i < 2; i++) {
#pragma unroll
        for (int j = 0; j < 2; j++) {
            int b = m0 + ty * 2 + i;
            int h = n0 + tx * 2 + j;
            size_t bh = (size_t)b * H_ + h;

            float ft = acc[0][i][j] + xp[((size_t)0 * B_ + b) * H_ + h];
            float it = acc[1][i][j] + xp[((size_t)1 * B_ + b) * H_ + h];
            float ot = acc[2][i][j] + xp[((size_t)2 * B_ + b) * H_ + h];
            float zt = acc[3][i][j] + xp[((size_t)3 * B_ + b) * H_ + h];

            float o  = 1.f / (1.f + expf(-ot));
            float z  = tanhf(zt);
            float fh = expf(fminf(ft, 10.f));
            float ih = expf(fminf(it, 10.f));
            float denom = fh + ih + 1e-8f;
            float f  = fh / denom;
            float ii = ih / denom;

            float c = f * g_c[bh] + ii * z;
            float n = f * g_n[bh] + ii;
            g_c[bh] = c;
            g_n[bh] = n;
            h_out[bh] = o * (c / (n + 1e-8f));
        }
    }
}

// ---------------------------------------------------------------------------
// Head: out[b] = tanh(h_final[b] . fc_w + fc_b). Final h is g_h[0]
// (t=511 has par=1, writes par^1=0).
// ---------------------------------------------------------------------------
__global__ __launch_bounds__(128) void head_kernel(
    const float* __restrict__ fcw, const float* __restrict__ fcb,
    float* __restrict__ out)
{
    int b = blockIdx.x;
    const float* __restrict__ h = g_h[0];
    float s = 0.f;
    for (int k = threadIdx.x; k < H_; k += 128)
        s += h[(size_t)b * H_ + k] * fcw[k];

    __shared__ float red[4];
#pragma unroll
    for (int off = 16; off; off >>= 1)
        s += __shfl_down_sync(0xffffffff, s, off);
    if ((threadIdx.x & 31) == 0) red[threadIdx.x >> 5] = s;
    __syncthreads();
    if (threadIdx.x == 0) {
        float tot = red[0] + red[1] + red[2] + red[3];
        out[b] = tanhf(tot + fcb[0]);
    }
}

// ---------------------------------------------------------------------------
extern "C" void kernel_launch(void* const* d_in, const int* in_sizes, int n_in,
                              void* d_out, int out_size)
{
    const float* x   = (const float*)d_in[0];
    const float* Wf  = (const float*)d_in[1];
    const float* bf  = (const float*)d_in[2];
    const float* Wi  = (const float*)d_in[3];
    const float* bi  = (const float*)d_in[4];
    const float* Wo  = (const float*)d_in[5];
    const float* bo  = (const float*)d_in[6];
    const float* Wz  = (const float*)d_in[7];
    const float* bz  = (const float*)d_in[8];
    const float* Rf  = (const float*)d_in[9];
    const float* Ri  = (const float*)d_in[10];
    const float* Ro  = (const float*)d_in[11];
    const float* Rz  = (const float*)d_in[12];
    const float* fcw = (const float*)d_in[13];
    const float* fcb = (const float*)d_in[14];
    float* out = (float*)d_out;

    init_kernel<<<(B_ * H_ + 255) / 256, 256>>>();

    dim3 gA(32, (B_ * T_) / 64);   // (4 gates * 8 n-tiles, 1024 m-tiles)
    proj_kernel<<<gA, 256>>>(x, Wf, bf, Wi, bi, Wo, bo, Wz, bz);

    dim3 gS(H_ / 32, B_ / 16);     // 16 x 8 = 128 blocks
    for (int t = 0; t < T_; t++)
        step_kernel<<<gS, 128>>>(t, t & 1, Rf, Ri, Ro, Rz);

    head_kernel<<<B_, 128>>>(fcw, fcb, out);
}